// round 9
// baseline (speedup 1.0000x reference)
#include <cuda_runtime.h>
#include <cuda_bf16.h>
#include <stdint.h>
#include <math.h>

#define BB 4
#define HH 8
#define SS 1024
#define DD 512
#define DKK 64

typedef __nv_bfloat16 bf;

// Scratch (allocation-free rule: __device__ globals)
__device__ bf g_vh[BB*HH*DKK*SS];   // V projected, split hi, transposed [b][h][dk][s]
__device__ bf g_vl[BB*HH*DKK*SS];   // V projected, split lo
__device__ bf g_xh[BB*SS*DD];       // attn out, split hi, [b][s][h*64+dk]
__device__ bf g_xl[BB*SS*DD];       // attn out, split lo
__device__ bf g_ah[BB*SS*DD];       // value pre-split hi
__device__ bf g_al[BB*SS*DD];       // value pre-split lo
__device__ bf g_wvh[DD*DD];         // W_v pre-split
__device__ bf g_wvl[DD*DD];
__device__ bf g_woh[DD*DD];         // W_o pre-split
__device__ bf g_wol[DD*DD];

__device__ __forceinline__ uint32_t pack_bf(bf a, bf b) {
    return (uint32_t)__bfloat16_as_ushort(a) | ((uint32_t)__bfloat16_as_ushort(b) << 16);
}
__device__ __forceinline__ void split1(float x, bf& h, bf& l) {
    h = __float2bfloat16(x);
    l = __float2bfloat16(x - __bfloat162float(h));
}

__device__ __forceinline__ void mma16816(float* d, const uint32_t* a, const uint32_t* b) {
    asm volatile(
        "mma.sync.aligned.m16n8k16.row.col.f32.bf16.bf16.f32 "
        "{%0,%1,%2,%3}, {%4,%5,%6,%7}, {%8,%9}, {%0,%1,%2,%3};"
        : "+f"(d[0]), "+f"(d[1]), "+f"(d[2]), "+f"(d[3])
        : "r"(a[0]), "r"(a[1]), "r"(a[2]), "r"(a[3]), "r"(b[0]), "r"(b[1]));
}

__device__ __forceinline__ uint32_t smem_u32(const void* p) {
    uint32_t a;
    asm("{ .reg .u64 t; cvta.to.shared.u64 t, %1; cvt.u32.u64 %0, t; }" : "=r"(a) : "l"(p));
    return a;
}
__device__ __forceinline__ void cp16(void* s, const void* g) {
    uint32_t sa = smem_u32(s);
    asm volatile("cp.async.cg.shared.global [%0], [%1], 16;" :: "r"(sa), "l"(g));
}
#define CP_COMMIT() asm volatile("cp.async.commit_group;" ::: "memory")

// ======================= prep: fp32 -> bf16 hi/lo split =======================
#define N_A4 (BB*SS*DD/4)
#define N_W4 (DD*DD/4)
__global__ void __launch_bounds__(256) split_prep(const float* __restrict__ value,
                                                  const float* __restrict__ Wv,
                                                  const float* __restrict__ Wo)
{
    int i = blockIdx.x * 256 + threadIdx.x;
    const float* src; bf *dh, *dl; int base;
    if (i < N_A4)            { src = value; dh = g_ah;  dl = g_al;  base = i; }
    else if (i < N_A4+N_W4)  { src = Wv;    dh = g_wvh; dl = g_wvl; base = i - N_A4; }
    else                     { src = Wo;    dh = g_woh; dl = g_wol; base = i - N_A4 - N_W4; }
    float4 v = ((const float4*)src)[base];
    bf h0,h1,h2,h3,l0,l1,l2,l3;
    split1(v.x,h0,l0); split1(v.y,h1,l1); split1(v.z,h2,l2); split1(v.w,h3,l3);
    *(uint2*)&dh[(size_t)base*4] = make_uint2(pack_bf(h0,h1), pack_bf(h2,h3));
    *(uint2*)&dl[(size_t)base*4] = make_uint2(pack_bf(l0,l1), pack_bf(l2,l3));
}

// ====== tensor-core GEMM, pre-split bf16, 4-slot cp.async ring, 16 warps k-split ======
// 512 threads: 16 warps = 4(m) x 2(n) x 2(k-half). Cross-k reduce via smem at end.
#define AST 40
#define GBUF (128 * AST)
#define GSLOT (4 * GBUF)
#define GEMM_SMEM (4 * GSLOT * 2)

template<int MODE>
__global__ void __launch_bounds__(512) gemm_bf(const bf* __restrict__ Ah,
                                               const bf* __restrict__ Al,
                                               const bf* __restrict__ Wh,
                                               const bf* __restrict__ Wl,
                                               const float* __restrict__ bv,
                                               float* __restrict__ Cout)
{
    extern __shared__ __align__(16) char smem[];
    const int t = threadIdx.x, wid = t >> 5, lane = t & 31;
    const int sub = wid & 7;              // compute-tile id (shared by both k-halves)
    const int wm = sub & 3, wn = sub >> 2;
    const int wk = wid >> 3;              // k-half
    const int n0 = blockIdx.x * 128, m0 = blockIdx.y * 128;
    const int gr = lane >> 2, gc = (lane & 3) * 2;

    float acc[2][8][4];
    #pragma unroll
    for (int i = 0; i < 2; i++)
        #pragma unroll
        for (int j = 0; j < 8; j++)
            #pragma unroll
            for (int q = 0; q < 4; q++) acc[i][j][q] = 0.f;

    // 512 threads: each fills one 16B segment per buffer (4 buffers)
    auto fill = [&](int slot, int k0) {
        char* sp = smem + slot * (GSLOT * 2);
        const int row = t >> 2, seg = t & 3;
        #pragma unroll
        for (int buf = 0; buf < 4; buf++) {
            const bf* s = (buf == 0) ? Ah + (size_t)(m0 + row) * 512
                        : (buf == 1) ? Al + (size_t)(m0 + row) * 512
                        : (buf == 2) ? Wh + (size_t)(n0 + row) * 512
                                     : Wl + (size_t)(n0 + row) * 512;
            cp16(sp + buf * (GBUF * 2) + row * (AST * 2) + seg * 16, s + k0 + seg * 8);
        }
    };

    fill(0, 0);  CP_COMMIT();
    fill(1, 32); CP_COMMIT();

    for (int c = 0; c < 16; c++) {
        if (c + 2 < 16) { fill((c + 2) & 3, (c + 2) * 32); CP_COMMIT(); }
        if (c < 14)      asm volatile("cp.async.wait_group 2;" ::: "memory");
        else if (c == 14) asm volatile("cp.async.wait_group 1;" ::: "memory");
        else              asm volatile("cp.async.wait_group 0;" ::: "memory");
        __syncthreads();

        char* sp  = smem + (c & 3) * (GSLOT * 2);
        bf* Ahi = (bf*)sp;
        bf* Alo = Ahi + GBUF;
        bf* Bhi = Alo + GBUF;
        bf* Blo = Bhi + GBUF;

        const int kk = wk * 16;    // this warp's k16 half of the 32-chunk
        uint32_t ah[2][4], al[2][4], bh[8][2], bl[8][2];
        #pragma unroll
        for (int mi = 0; mi < 2; mi++) {
            int r = wm * 32 + mi * 16 + gr;
            ah[mi][0] = *(const uint32_t*)&Ahi[(r    ) * AST + kk + gc];
            ah[mi][1] = *(const uint32_t*)&Ahi[(r + 8) * AST + kk + gc];
            ah[mi][2] = *(const uint32_t*)&Ahi[(r    ) * AST + kk + gc + 8];
            ah[mi][3] = *(const uint32_t*)&Ahi[(r + 8) * AST + kk + gc + 8];
        }
        #pragma unroll
        for (int nj = 0; nj < 8; nj++) {
            int r = wn * 64 + nj * 8 + gr;
            bh[nj][0] = *(const uint32_t*)&Bhi[r * AST + kk + gc];
            bh[nj][1] = *(const uint32_t*)&Bhi[r * AST + kk + gc + 8];
        }
        #pragma unroll
        for (int mi = 0; mi < 2; mi++)
            #pragma unroll
            for (int nj = 0; nj < 8; nj++) mma16816(acc[mi][nj], ah[mi], bh[nj]);

        #pragma unroll
        for (int nj = 0; nj < 8; nj++) {
            int r = wn * 64 + nj * 8 + gr;
            bl[nj][0] = *(const uint32_t*)&Blo[r * AST + kk + gc];
            bl[nj][1] = *(const uint32_t*)&Blo[r * AST + kk + gc + 8];
        }
        #pragma unroll
        for (int mi = 0; mi < 2; mi++)
            #pragma unroll
            for (int nj = 0; nj < 8; nj++) mma16816(acc[mi][nj], ah[mi], bl[nj]);

        #pragma unroll
        for (int mi = 0; mi < 2; mi++) {
            int r = wm * 32 + mi * 16 + gr;
            al[mi][0] = *(const uint32_t*)&Alo[(r    ) * AST + kk + gc];
            al[mi][1] = *(const uint32_t*)&Alo[(r + 8) * AST + kk + gc];
            al[mi][2] = *(const uint32_t*)&Alo[(r    ) * AST + kk + gc + 8];
            al[mi][3] = *(const uint32_t*)&Alo[(r + 8) * AST + kk + gc + 8];
        }
        #pragma unroll
        for (int mi = 0; mi < 2; mi++)
            #pragma unroll
            for (int nj = 0; nj < 8; nj++) mma16816(acc[mi][nj], al[mi], bh[nj]);
    }

    // ---- cross-k reduce: wk=1 dumps acc, wk=0 adds + epilogue ----
    __syncthreads();
    float* red = (float*)smem;
    const int rid = sub * 32 + lane;    // 0..255
    if (wk == 1) {
        float* dst = red + rid * 68;
        #pragma unroll
        for (int mi = 0; mi < 2; mi++)
            #pragma unroll
            for (int nj = 0; nj < 8; nj++)
                *(float4*)&dst[(mi * 8 + nj) * 4] = *(float4*)acc[mi][nj];
    }
    __syncthreads();
    if (wk == 0) {
        const float* src = red + rid * 68;
        #pragma unroll
        for (int mi = 0; mi < 2; mi++)
            #pragma unroll
            for (int nj = 0; nj < 8; nj++) {
                float4 v = *(const float4*)&src[(mi * 8 + nj) * 4];
                acc[mi][nj][0] += v.x; acc[mi][nj][1] += v.y;
                acc[mi][nj][2] += v.z; acc[mi][nj][3] += v.w;
            }

        #pragma unroll
        for (int mi = 0; mi < 2; mi++) {
            int r0 = m0 + wm * 32 + mi * 16 + gr;
            #pragma unroll
            for (int nj = 0; nj < 8; nj++) {
                int n = n0 + wn * 64 + nj * 8 + gc;
                float v00 = acc[mi][nj][0] + bv[n];
                float v01 = acc[mi][nj][1] + bv[n + 1];
                float v10 = acc[mi][nj][2] + bv[n];
                float v11 = acc[mi][nj][3] + bv[n + 1];
                if (MODE == 0) {
                    int h_ = n >> 6, d_ = n & 63;
                    int b0_ = r0 >> 10, s0_ = r0 & 1023;
                    int b1_ = (r0 + 8) >> 10, s1_ = (r0 + 8) & 1023;
                    size_t p00 = (((size_t)(b0_ * HH + h_) * DKK) + d_) * SS + s0_;
                    size_t p01 = (((size_t)(b0_ * HH + h_) * DKK) + d_ + 1) * SS + s0_;
                    size_t p10 = (((size_t)(b1_ * HH + h_) * DKK) + d_) * SS + s1_;
                    size_t p11 = (((size_t)(b1_ * HH + h_) * DKK) + d_ + 1) * SS + s1_;
                    bf hh, ll;
                    split1(v00, hh, ll); g_vh[p00] = hh; g_vl[p00] = ll;
                    split1(v01, hh, ll); g_vh[p01] = hh; g_vl[p01] = ll;
                    split1(v10, hh, ll); g_vh[p10] = hh; g_vl[p10] = ll;
                    split1(v11, hh, ll); g_vh[p11] = hh; g_vl[p11] = ll;
                } else {
                    Cout[(size_t)r0 * 512 + n]           = v00;
                    Cout[(size_t)r0 * 512 + n + 1]       = v01;
                    Cout[(size_t)(r0 + 8) * 512 + n]     = v10;
                    Cout[(size_t)(r0 + 8) * 512 + n + 1] = v11;
                }
            }
        }
    }
}

// ====== attention v5: bias-only cp.async stage, mask via early L2 LDG, 3 CTAs/SM ======
// 8 warps = 2(m) x 2(n) x 2(k-half). Cross-k reduction at kernel end via smem.
#define PST 72
#define SST 68
#define STAGE_ELEMS (64 * SST)
#define ATTN_SMEM (2 * STAGE_ELEMS * 4 + 4 * 64 * PST * 2 + 256)

__global__ void __launch_bounds__(256, 3) attn5(const float* __restrict__ bias,
                                                const int*   __restrict__ mask,
                                                float*       __restrict__ bias_out)
{
    extern __shared__ __align__(16) char smem[];
    float* stB  = (float*)smem;                       // 2 stages bias only
    bf*    Ph   = (bf*)(smem + 2 * STAGE_ELEMS * 4);
    bf*    Pl   = Ph + 64 * PST;
    bf*    Vh   = Pl + 64 * PST;
    bf*    Vl   = Vh + 64 * PST;
    float* lsum = (float*)(Vl + 64 * PST);

    const int t = threadIdx.x, wid = t >> 5, lane = t & 31;
    const int gr = lane >> 2, gc = (lane & 3) * 2;
    const int wk = wid >> 2;
    const int wm = (wid >> 1) & 1;
    const int wn = wid & 1;
    const int q0 = blockIdx.x * 64;
    const int h  = blockIdx.y;
    const int b  = blockIdx.z;

    const float* __restrict__ bias_base = bias     + (((size_t)(b * HH + h)) * SS + q0) * SS;
    float*       __restrict__ bout_base = bias_out + (((size_t)(b * HH + h)) * SS + q0) * SS;
    const int*   __restrict__ mask_base = mask     + ((size_t)(b * SS + q0)) * SS;
    const bf*    __restrict__ vh_base   = g_vh + ((size_t)(b * HH + h) * DKK) * SS;
    const bf*    __restrict__ vl_base   = g_vl + ((size_t)(b * HH + h) * DKK) * SS;

    const int prow = t >> 2;
    const int pc0  = (t & 3) * 16;
    const int vrow = t >> 2;
    const int vc0  = (t & 3) * 16;

    float rsum = 0.f;
    float acc[2][4][4];
    #pragma unroll
    for (int i = 0; i < 2; i++)
        #pragma unroll
        for (int j = 0; j < 4; j++)
            #pragma unroll
            for (int q = 0; q < 4; q++) acc[i][j][q] = 0.f;

    {
        #pragma unroll
        for (int i = 0; i < 4; i++) {
            int o = t + i * 256; int row = o >> 4, seg = o & 15;
            cp16(&stB[row * SST + seg * 4], &bias_base[(size_t)row * SS + seg * 4]);
        }
        CP_COMMIT();
    }

    for (int c = 0; c < 16; c++) {
        const int k0 = c * 64;
        if (c < 15) {
            float* dB = stB + ((c + 1) & 1) * STAGE_ELEMS;
            #pragma unroll
            for (int i = 0; i < 4; i++) {
                int o = t + i * 256; int row = o >> 4, seg = o & 15;
                cp16(&dB[row * SST + seg * 4], &bias_base[(size_t)row * SS + k0 + 64 + seg * 4]);
            }
            CP_COMMIT();
            asm volatile("cp.async.wait_group 1;" ::: "memory");
        } else {
            asm volatile("cp.async.wait_group 0;" ::: "memory");
        }
        __syncthreads();   // stage ready; prev MMA done (P/V safe to overwrite)

        // ---- early global loads: V (L2) + mask (L2, shared across heads) ----
        uint4 vh0, vh1, vl0, vl1;
        int4 m4[4];
        {
            const bf* vh_p = vh_base + (size_t)vrow * SS + k0 + vc0;
            const bf* vl_p = vl_base + (size_t)vrow * SS + k0 + vc0;
            vh0 = *(const uint4*)(vh_p);
            vh1 = *(const uint4*)(vh_p + 8);
            vl0 = *(const uint4*)(vl_p);
            vl1 = *(const uint4*)(vl_p + 8);
            const int* mp = mask_base + (size_t)prow * SS + k0 + pc0;
            #pragma unroll
            for (int g = 0; g < 4; g++) m4[g] = *(const int4*)(mp + g * 4);
        }

        // ---- P gen from staged bias (+ bias copy-out) ----
        const float* sB = stB + (c & 1) * STAGE_ELEMS + prow * SST + pc0;
        float*       bo = bout_base + (size_t)prow * SS + k0 + pc0;
        #pragma unroll
        for (int g = 0; g < 4; g++) {
            float4 b4 = *(const float4*)(sB + g * 4);
            *(float4*)(bo + g * 4) = b4;
            float p0 = m4[g].x ? __expf(b4.x) : 0.f;
            float p1 = m4[g].y ? __expf(b4.y) : 0.f;
            float p2 = m4[g].z ? __expf(b4.z) : 0.f;
            float p3 = m4[g].w ? __expf(b4.w) : 0.f;
            rsum += (p0 + p1) + (p2 + p3);
            bf h0,h1,h2,h3,l0,l1,l2,l3;
            split1(p0,h0,l0); split1(p1,h1,l1); split1(p2,h2,l2); split1(p3,h3,l3);
            *(uint2*)&Ph[prow * PST + pc0 + g * 4] = make_uint2(pack_bf(h0,h1), pack_bf(h2,h3));
            *(uint2*)&Pl[prow * PST + pc0 + g * 4] = make_uint2(pack_bf(l0,l1), pack_bf(l2,l3));
        }

        // ---- store V (arrived by now) ----
        *(uint4*)&Vh[vrow * PST + vc0]     = vh0;
        *(uint4*)&Vh[vrow * PST + vc0 + 8] = vh1;
        *(uint4*)&Vl[vrow * PST + vc0]     = vl0;
        *(uint4*)&Vl[vrow * PST + vc0 + 8] = vl1;
        __syncthreads();

        // ---- MMA: warp tile m32 x n32 x k32(half), 2 k16 steps, 3 passes ----
        const int qb = wm * 32, vb = wn * 32, kb = wk * 32;
        #pragma unroll
        for (int kks = 0; kks < 32; kks += 16) {
            const int kk = kb + kks;
            uint32_t ah[2][4], al[2][4], bh[4][2], bl[4][2];
            #pragma unroll
            for (int mi = 0; mi < 2; mi++) {
                int r = qb + mi * 16 + gr;
                ah[mi][0] = *(const uint32_t*)&Ph[(r    ) * PST + kk + gc];
                ah[mi][1] = *(const uint32_t*)&Ph[(r + 8) * PST + kk + gc];
                ah[mi][2] = *(const uint32_t*)&Ph[(r    ) * PST + kk + gc + 8];
                ah[mi][3] = *(const uint32_t*)&Ph[(r + 8) * PST + kk + gc + 8];
            }
            #pragma unroll
            for (int nj = 0; nj < 4; nj++) {
                int r = vb + nj * 8 + gr;
                bh[nj][0] = *(const uint32_t*)&Vh[r * PST + kk + gc];
                bh[nj][1] = *(const uint32_t*)&Vh[r * PST + kk + gc + 8];
            }
            #pragma unroll
            for (int mi = 0; mi < 2; mi++)
                #pragma unroll
                for (int nj = 0; nj < 4; nj++) mma16816(acc[mi][nj], ah[mi], bh[nj]);

            #pragma unroll
            for (int nj = 0; nj < 4; nj++) {
                int r = vb + nj * 8 + gr;
                bl[nj][0] = *(const uint32_t*)&Vl[r * PST + kk + gc];
                bl[nj][1] = *(const uint32_t*)&Vl[r * PST + kk + gc + 8];
            }
            #pragma unroll
            for (int mi = 0; mi < 2; mi++)
                #pragma unroll
                for (int nj = 0; nj < 4; nj++) mma16816(acc[mi][nj], ah[mi], bl[nj]);

            #pragma unroll
            for (int mi = 0; mi < 2; mi++) {
                int r = qb + mi * 16 + gr;
                al[mi][0] = *(const uint32_t*)&Pl[(r    ) * PST + kk + gc];
                al[mi][1] = *(const uint32_t*)&Pl[(r + 8) * PST + kk + gc];
                al[mi][2] = *(const uint32_t*)&Pl[(r    ) * PST + kk + gc + 8];
                al[mi][3] = *(const uint32_t*)&Pl[(r + 8) * PST + kk + gc + 8];
            }
            #pragma unroll
            for (int mi = 0; mi < 2; mi++)
                #pragma unroll
                for (int nj = 0; nj < 4; nj++) mma16816(acc[mi][nj], al[mi], bh[nj]);
        }
    }

    // ---- rowsum combine ----
    rsum += __shfl_xor_sync(0xffffffffu, rsum, 1);
    rsum += __shfl_xor_sync(0xffffffffu, rsum, 2);
    if ((t & 3) == 0) lsum[prow] = rsum;

    // ---- cross-k reduction ----
    float* red = stB;
    const int w4 = wid & 3;
    __syncthreads();
    if (wk == 1) {
        float* dst = red + (w4 * 32 + lane) * 36;
        #pragma unroll
        for (int mi = 0; mi < 2; mi++)
            #pragma unroll
            for (int nj = 0; nj < 4; nj++)
                *(float4*)&dst[(mi * 4 + nj) * 4] = *(float4*)acc[mi][nj];
    }
    __syncthreads();
    if (wk == 0) {
        const float* src = red + (w4 * 32 + lane) * 36;
        #pragma unroll
        for (int mi = 0; mi < 2; mi++)
            #pragma unroll
            for (int nj = 0; nj < 4; nj++) {
                float4 v = *(const float4*)&src[(mi * 4 + nj) * 4];
                acc[mi][nj][0] += v.x; acc[mi][nj][1] += v.y;
                acc[mi][nj][2] += v.z; acc[mi][nj][3] += v.w;
            }

        const int qb = wm * 32, vb = wn * 32;
        #pragma unroll
        for (int mi = 0; mi < 2; mi++) {
            const int r0 = qb + mi * 16 + gr;
            const float inv0 = 1.f / lsum[r0];
            const float inv1 = 1.f / lsum[r0 + 8];
            #pragma unroll
            for (int nj = 0; nj < 4; nj++) {
                int dk = vb + nj * 8 + gc;
                size_t o0 = ((size_t)(b * SS + q0 + r0)) * DD + h * 64 + dk;
                size_t o1 = ((size_t)(b * SS + q0 + r0 + 8)) * DD + h * 64 + dk;
                bf h0,l0,h1,l1;
                split1(acc[mi][nj][0] * inv0, h0, l0); split1(acc[mi][nj][1] * inv0, h1, l1);
                *(uint32_t*)&g_xh[o0] = pack_bf(h0, h1);
                *(uint32_t*)&g_xl[o0] = pack_bf(l0, l1);
                split1(acc[mi][nj][2] * inv1, h0, l0); split1(acc[mi][nj][3] * inv1, h1, l1);
                *(uint32_t*)&g_xh[o1] = pack_bf(h0, h1);
                *(uint32_t*)&g_xl[o1] = pack_bf(l0, l1);
            }
        }
    }
}

extern "C" void kernel_launch(void* const* d_in, const int* in_sizes, int n_in,
                              void* d_out, int out_size)
{
    // metadata order: query, key, value, bias, mask, W_v, b_v, W_o, b_o
    const float* value = (const float*)d_in[2];
    const float* bias  = (const float*)d_in[3];
    const int*   mask  = (const int*)  d_in[4];
    const float* W_v   = (const float*)d_in[5];
    const float* b_v   = (const float*)d_in[6];
    const float* W_o   = (const float*)d_in[7];
    const float* b_o   = (const float*)d_in[8];

    float* out      = (float*)d_out;                 // [B,S,D]
    float* bias_out = out + (size_t)BB * SS * DD;    // [B,H,S,S]

    cudaFuncSetAttribute(gemm_bf<0>, cudaFuncAttributeMaxDynamicSharedMemorySize, GEMM_SMEM);
    cudaFuncSetAttribute(gemm_bf<1>, cudaFuncAttributeMaxDynamicSharedMemorySize, GEMM_SMEM);
    cudaFuncSetAttribute(attn5, cudaFuncAttributeMaxDynamicSharedMemorySize, ATTN_SMEM);

    bf *p_ah, *p_al, *p_wvh, *p_wvl, *p_woh, *p_wol, *p_xh, *p_xl;
    cudaGetSymbolAddress((void**)&p_ah,  g_ah);
    cudaGetSymbolAddress((void**)&p_al,  g_al);
    cudaGetSymbolAddress((void**)&p_wvh, g_wvh);
    cudaGetSymbolAddress((void**)&p_wvl, g_wvl);
    cudaGetSymbolAddress((void**)&p_woh, g_woh);
    cudaGetSymbolAddress((void**)&p_wol, g_wol);
    cudaGetSymbolAddress((void**)&p_xh,  g_xh);
    cudaGetSymbolAddress((void**)&p_xl,  g_xl);

    // 0) pre-split value, W_v, W_o
    split_prep<<<(N_A4 + 2 * N_W4 + 255) / 256, 256>>>(value, W_v, W_o);

    // 1) V projection -> g_vh/g_vl [b][h][dk][s]
    gemm_bf<0><<<dim3(4, 32), 512, GEMM_SMEM>>>(p_ah, p_al, p_wvh, p_wvl, b_v, nullptr);

    // 2) masked softmax(bias) @ v (+ fused bias copy) -> g_xh/g_xl
    attn5<<<dim3(SS / 64, HH, BB), 256, ATTN_SMEM>>>(bias, mask, bias_out);

    // 3) O projection -> out
    gemm_bf<1><<<dim3(4, 32), 512, GEMM_SMEM>>>(p_xh, p_xl, p_woh, p_wol, b_o, out);
}

// round 11
// speedup vs baseline: 1.2956x; 1.2956x over previous
#include <cuda_runtime.h>
#include <cuda_bf16.h>
#include <cuda_fp16.h>
#include <stdint.h>
#include <math.h>

#define BB 4
#define HH 8
#define SS 1024
#define DD 512
#define DKK 64

typedef __nv_bfloat16 bf;

// Scratch (allocation-free rule: __device__ globals)
__device__ __half g_vf[BB*HH*DKK*SS]; // V projected, fp16, transposed [b][h][dk][s]
__device__ bf g_xh[BB*SS*DD];       // attn out, split hi, [b][s][h*64+dk]
__device__ bf g_xl[BB*SS*DD];       // attn out, split lo
__device__ bf g_ah[BB*SS*DD];       // value pre-split hi
__device__ bf g_al[BB*SS*DD];       // value pre-split lo
__device__ bf g_wvh[DD*DD];         // W_v pre-split
__device__ bf g_wvl[DD*DD];
__device__ bf g_woh[DD*DD];         // W_o pre-split
__device__ bf g_wol[DD*DD];

__device__ __forceinline__ uint32_t pack_bf(bf a, bf b) {
    return (uint32_t)__bfloat16_as_ushort(a) | ((uint32_t)__bfloat16_as_ushort(b) << 16);
}
__device__ __forceinline__ void split1(float x, bf& h, bf& l) {
    h = __float2bfloat16(x);
    l = __float2bfloat16(x - __bfloat162float(h));
}
__device__ __forceinline__ uint32_t pack_h2(float lo, float hi) {
    __half2 h = __floats2half2_rn(lo, hi);
    return *(uint32_t*)&h;
}

// bf16 MMA (projection GEMMs)
__device__ __forceinline__ void mma16816(float* d, const uint32_t* a, const uint32_t* b) {
    asm volatile(
        "mma.sync.aligned.m16n8k16.row.col.f32.bf16.bf16.f32 "
        "{%0,%1,%2,%3}, {%4,%5,%6,%7}, {%8,%9}, {%0,%1,%2,%3};"
        : "+f"(d[0]), "+f"(d[1]), "+f"(d[2]), "+f"(d[3])
        : "r"(a[0]), "r"(a[1]), "r"(a[2]), "r"(a[3]), "r"(b[0]), "r"(b[1]));
}
// fp16 MMA (PV)
__device__ __forceinline__ void mma16816h(float* d, const uint32_t* a, const uint32_t* b) {
    asm volatile(
        "mma.sync.aligned.m16n8k16.row.col.f32.f16.f16.f32 "
        "{%0,%1,%2,%3}, {%4,%5,%6,%7}, {%8,%9}, {%0,%1,%2,%3};"
        : "+f"(d[0]), "+f"(d[1]), "+f"(d[2]), "+f"(d[3])
        : "r"(a[0]), "r"(a[1]), "r"(a[2]), "r"(a[3]), "r"(b[0]), "r"(b[1]));
}

__device__ __forceinline__ uint32_t smem_u32(const void* p) {
    uint32_t a;
    asm("{ .reg .u64 t; cvta.to.shared.u64 t, %1; cvt.u32.u64 %0, t; }" : "=r"(a) : "l"(p));
    return a;
}
__device__ __forceinline__ void cp16(void* s, const void* g) {
    uint32_t sa = smem_u32(s);
    asm volatile("cp.async.cg.shared.global [%0], [%1], 16;" :: "r"(sa), "l"(g));
}
#define CP_COMMIT() asm volatile("cp.async.commit_group;" ::: "memory")

// ======================= prep: fp32 -> bf16 hi/lo split =======================
#define N_A4 (BB*SS*DD/4)
#define N_W4 (DD*DD/4)
__global__ void __launch_bounds__(256) split_prep(const float* __restrict__ value,
                                                  const float* __restrict__ Wv,
                                                  const float* __restrict__ Wo)
{
    int i = blockIdx.x * 256 + threadIdx.x;
    const float* src; bf *dh, *dl; int base;
    if (i < N_A4)            { src = value; dh = g_ah;  dl = g_al;  base = i; }
    else if (i < N_A4+N_W4)  { src = Wv;    dh = g_wvh; dl = g_wvl; base = i - N_A4; }
    else                     { src = Wo;    dh = g_woh; dl = g_wol; base = i - N_A4 - N_W4; }
    float4 v = ((const float4*)src)[base];
    bf h0,h1,h2,h3,l0,l1,l2,l3;
    split1(v.x,h0,l0); split1(v.y,h1,l1); split1(v.z,h2,l2); split1(v.w,h3,l3);
    *(uint2*)&dh[(size_t)base*4] = make_uint2(pack_bf(h0,h1), pack_bf(h2,h3));
    *(uint2*)&dl[(size_t)base*4] = make_uint2(pack_bf(l0,l1), pack_bf(l2,l3));
}

// ============== tensor-core GEMM on pre-split bf16, 4-slot cp.async ring =========
// (R8 configuration: 256 threads, 8 warps 4m x 2n — best measured)
// MODE 0: write V as fp16 transposed [b][h][dk][s]. MODE 1: Cout fp32.
#define AST 40
#define GBUF (128 * AST)
#define GSLOT (4 * GBUF)
#define GEMM_SMEM (4 * GSLOT * 2)

template<int MODE>
__global__ void __launch_bounds__(256) gemm_bf(const bf* __restrict__ Ah,
                                               const bf* __restrict__ Al,
                                               const bf* __restrict__ Wh,
                                               const bf* __restrict__ Wl,
                                               const float* __restrict__ bv,
                                               float* __restrict__ Cout)
{
    extern __shared__ __align__(16) char smem[];
    const int t = threadIdx.x, wid = t >> 5, lane = t & 31;
    const int wm = wid & 3, wn = wid >> 2;
    const int n0 = blockIdx.x * 128, m0 = blockIdx.y * 128;
    const int gr = lane >> 2, gc = (lane & 3) * 2;

    float acc[2][8][4];
    #pragma unroll
    for (int i = 0; i < 2; i++)
        #pragma unroll
        for (int j = 0; j < 8; j++)
            #pragma unroll
            for (int q = 0; q < 4; q++) acc[i][j][q] = 0.f;

    auto fill = [&](int slot, int k0) {
        char* sp = smem + slot * (GSLOT * 2);
        #pragma unroll
        for (int i = 0; i < 8; i++) {
            const int buf = i >> 1;
            const int id  = t + (i & 1) * 256;
            const int row = id >> 2, seg = id & 3;
            const bf* s = (buf == 0) ? Ah + (size_t)(m0 + row) * 512
                        : (buf == 1) ? Al + (size_t)(m0 + row) * 512
                        : (buf == 2) ? Wh + (size_t)(n0 + row) * 512
                                     : Wl + (size_t)(n0 + row) * 512;
            cp16(sp + buf * (GBUF * 2) + row * (AST * 2) + seg * 16, s + k0 + seg * 8);
        }
    };

    fill(0, 0);  CP_COMMIT();
    fill(1, 32); CP_COMMIT();

    for (int c = 0; c < 16; c++) {
        if (c + 2 < 16) { fill((c + 2) & 3, (c + 2) * 32); CP_COMMIT(); }
        if (c < 14)      asm volatile("cp.async.wait_group 2;" ::: "memory");
        else if (c == 14) asm volatile("cp.async.wait_group 1;" ::: "memory");
        else              asm volatile("cp.async.wait_group 0;" ::: "memory");
        __syncthreads();

        char* sp  = smem + (c & 3) * (GSLOT * 2);
        bf* Ahi = (bf*)sp;
        bf* Alo = Ahi + GBUF;
        bf* Bhi = Alo + GBUF;
        bf* Blo = Bhi + GBUF;

        #pragma unroll
        for (int kk = 0; kk < 32; kk += 16) {
            uint32_t ah[2][4], al[2][4], bh[8][2], bl[8][2];
            #pragma unroll
            for (int mi = 0; mi < 2; mi++) {
                int r = wm * 32 + mi * 16 + gr;
                ah[mi][0] = *(const uint32_t*)&Ahi[(r    ) * AST + kk + gc];
                ah[mi][1] = *(const uint32_t*)&Ahi[(r + 8) * AST + kk + gc];
                ah[mi][2] = *(const uint32_t*)&Ahi[(r    ) * AST + kk + gc + 8];
                ah[mi][3] = *(const uint32_t*)&Ahi[(r + 8) * AST + kk + gc + 8];
            }
            #pragma unroll
            for (int nj = 0; nj < 8; nj++) {
                int r = wn * 64 + nj * 8 + gr;
                bh[nj][0] = *(const uint32_t*)&Bhi[r * AST + kk + gc];
                bh[nj][1] = *(const uint32_t*)&Bhi[r * AST + kk + gc + 8];
            }
            #pragma unroll
            for (int mi = 0; mi < 2; mi++)
                #pragma unroll
                for (int nj = 0; nj < 8; nj++) mma16816(acc[mi][nj], ah[mi], bh[nj]);

            #pragma unroll
            for (int nj = 0; nj < 8; nj++) {
                int r = wn * 64 + nj * 8 + gr;
                bl[nj][0] = *(const uint32_t*)&Blo[r * AST + kk + gc];
                bl[nj][1] = *(const uint32_t*)&Blo[r * AST + kk + gc + 8];
            }
            #pragma unroll
            for (int mi = 0; mi < 2; mi++)
                #pragma unroll
                for (int nj = 0; nj < 8; nj++) mma16816(acc[mi][nj], ah[mi], bl[nj]);

            #pragma unroll
            for (int mi = 0; mi < 2; mi++) {
                int r = wm * 32 + mi * 16 + gr;
                al[mi][0] = *(const uint32_t*)&Alo[(r    ) * AST + kk + gc];
                al[mi][1] = *(const uint32_t*)&Alo[(r + 8) * AST + kk + gc];
                al[mi][2] = *(const uint32_t*)&Alo[(r    ) * AST + kk + gc + 8];
                al[mi][3] = *(const uint32_t*)&Alo[(r + 8) * AST + kk + gc + 8];
            }
            #pragma unroll
            for (int mi = 0; mi < 2; mi++)
                #pragma unroll
                for (int nj = 0; nj < 8; nj++) mma16816(acc[mi][nj], al[mi], bh[nj]);
        }
    }

    #pragma unroll
    for (int mi = 0; mi < 2; mi++) {
        int r0 = m0 + wm * 32 + mi * 16 + gr;
        #pragma unroll
        for (int nj = 0; nj < 8; nj++) {
            int n = n0 + wn * 64 + nj * 8 + gc;
            float v00 = acc[mi][nj][0] + bv[n];
            float v01 = acc[mi][nj][1] + bv[n + 1];
            float v10 = acc[mi][nj][2] + bv[n];
            float v11 = acc[mi][nj][3] + bv[n + 1];
            if (MODE == 0) {
                int h_ = n >> 6, d_ = n & 63;
                int b0_ = r0 >> 10, s0_ = r0 & 1023;
                int b1_ = (r0 + 8) >> 10, s1_ = (r0 + 8) & 1023;
                size_t p00 = (((size_t)(b0_ * HH + h_) * DKK) + d_) * SS + s0_;
                size_t p01 = (((size_t)(b0_ * HH + h_) * DKK) + d_ + 1) * SS + s0_;
                size_t p10 = (((size_t)(b1_ * HH + h_) * DKK) + d_) * SS + s1_;
                size_t p11 = (((size_t)(b1_ * HH + h_) * DKK) + d_ + 1) * SS + s1_;
                g_vf[p00] = __float2half(v00);
                g_vf[p01] = __float2half(v01);
                g_vf[p10] = __float2half(v10);
                g_vf[p11] = __float2half(v11);
            } else {
                Cout[(size_t)r0 * 512 + n]           = v00;
                Cout[(size_t)r0 * 512 + n + 1]       = v01;
                Cout[(size_t)(r0 + 8) * 512 + n]     = v10;
                Cout[(size_t)(r0 + 8) * 512 + n + 1] = v11;
            }
        }
    }
}

// ====== attention v7: R8 structure, fp16 single-pass PV (calibrated precision) ======
// 8 warps = 2(m) x 2(n) x 2(k-half). P = fp16(exp(bias) masked), V fp16.
// fp16 roundoff 2^-12; calibrated error ~0.85*2^-12*sqrt2 ~ 3e-4 << 1e-3.
#define PST 72
#define SST 68
#define STAGE_ELEMS (64 * SST)
#define ATTN_SMEM (4 * STAGE_ELEMS * 4 + 2 * 64 * PST * 2 + 256)

__global__ void __launch_bounds__(256, 2) attn7(const float* __restrict__ bias,
                                                const int*   __restrict__ mask,
                                                float*       __restrict__ bias_out)
{
    extern __shared__ __align__(16) char smem[];
    float*  stB  = (float*)smem;
    int*    stM  = (int*)(smem + 2 * STAGE_ELEMS * 4);
    __half* Ph   = (__half*)(smem + 4 * STAGE_ELEMS * 4);
    __half* Vf   = Ph + 64 * PST;
    float*  lsum = (float*)(Vf + 64 * PST);

    const int t = threadIdx.x, wid = t >> 5, lane = t & 31;
    const int gr = lane >> 2, gc = (lane & 3) * 2;
    const int wk = wid >> 2;            // k-half 0/1
    const int wm = (wid >> 1) & 1;      // m-half (32 q rows)
    const int wn = wid & 1;             // n-half (32 dk cols)
    const int q0 = blockIdx.x * 64;
    const int h  = blockIdx.y;
    const int b  = blockIdx.z;

    const float* __restrict__ bias_base = bias     + (((size_t)(b * HH + h)) * SS + q0) * SS;
    float*       __restrict__ bout_base = bias_out + (((size_t)(b * HH + h)) * SS + q0) * SS;
    const int*   __restrict__ mask_base = mask     + ((size_t)(b * SS + q0)) * SS;
    const __half* __restrict__ vf_base  = g_vf + ((size_t)(b * HH + h) * DKK) * SS;

    const int prow = t >> 2;
    const int pc0  = (t & 3) * 16;
    const int vrow = t >> 2;
    const int vc0  = (t & 3) * 16;

    float rsum = 0.f;
    float acc[2][4][4];
    #pragma unroll
    for (int i = 0; i < 2; i++)
        #pragma unroll
        for (int j = 0; j < 4; j++)
            #pragma unroll
            for (int q = 0; q < 4; q++) acc[i][j][q] = 0.f;

    {
        #pragma unroll
        for (int i = 0; i < 4; i++) {
            int o = t + i * 256; int row = o >> 4, seg = o & 15;
            cp16(&stB[row * SST + seg * 4], &bias_base[(size_t)row * SS + seg * 4]);
            cp16(&stM[row * SST + seg * 4], &mask_base[(size_t)row * SS + seg * 4]);
        }
        CP_COMMIT();
    }

    for (int c = 0; c < 16; c++) {
        const int k0 = c * 64;
        if (c < 15) {
            float* dB = stB + ((c + 1) & 1) * STAGE_ELEMS;
            int*   dM = stM + ((c + 1) & 1) * STAGE_ELEMS;
            #pragma unroll
            for (int i = 0; i < 4; i++) {
                int o = t + i * 256; int row = o >> 4, seg = o & 15;
                cp16(&dB[row * SST + seg * 4], &bias_base[(size_t)row * SS + k0 + 64 + seg * 4]);
                cp16(&dM[row * SST + seg * 4], &mask_base[(size_t)row * SS + k0 + 64 + seg * 4]);
            }
            CP_COMMIT();
            asm volatile("cp.async.wait_group 1;" ::: "memory");
        } else {
            asm volatile("cp.async.wait_group 0;" ::: "memory");
        }
        __syncthreads();   // stage ready; prev MMA done (P/V safe to overwrite)

        // ---- issue V LDGs early: latency hidden under P-gen ----
        uint4 vf0, vf1;
        {
            const __half* vf_p = vf_base + (size_t)vrow * SS + k0 + vc0;
            vf0 = *(const uint4*)(vf_p);
            vf1 = *(const uint4*)(vf_p + 8);
        }

        // ---- P gen from staged smem (+ bias copy-out); fp16 ----
        const float* sB = stB + (c & 1) * STAGE_ELEMS + prow * SST + pc0;
        const int*   sM = stM + (c & 1) * STAGE_ELEMS + prow * SST + pc0;
        float*       bo = bout_base + (size_t)prow * SS + k0 + pc0;
        #pragma unroll
        for (int g = 0; g < 4; g++) {
            float4 b4 = *(const float4*)(sB + g * 4);
            int4   m4 = *(const int4*)(sM + g * 4);
            *(float4*)(bo + g * 4) = b4;
            float p0 = m4.x ? __expf(b4.x) : 0.f;
            float p1 = m4.y ? __expf(b4.y) : 0.f;
            float p2 = m4.z ? __expf(b4.z) : 0.f;
            float p3 = m4.w ? __expf(b4.w) : 0.f;
            rsum += (p0 + p1) + (p2 + p3);
            *(uint2*)&Ph[prow * PST + pc0 + g * 4] = make_uint2(pack_h2(p0, p1), pack_h2(p2, p3));
        }

        // ---- store V (arrived by now) ----
        *(uint4*)&Vf[vrow * PST + vc0]     = vf0;
        *(uint4*)&Vf[vrow * PST + vc0 + 8] = vf1;
        __syncthreads();

        // ---- MMA: warp tile m32 x n32 x k32(half), 2 k16 steps, SINGLE pass ----
        const int qb = wm * 32, vb = wn * 32, kb = wk * 32;
        #pragma unroll
        for (int kks = 0; kks < 32; kks += 16) {
            const int kk = kb + kks;
            uint32_t ah[2][4], bh[4][2];
            #pragma unroll
            for (int mi = 0; mi < 2; mi++) {
                int r = qb + mi * 16 + gr;
                ah[mi][0] = *(const uint32_t*)&Ph[(r    ) * PST + kk + gc];
                ah[mi][1] = *(const uint32_t*)&Ph[(r + 8) * PST + kk + gc];
                ah[mi][2] = *(const uint32_t*)&Ph[(r    ) * PST + kk + gc + 8];
                ah[mi][3] = *(const uint32_t*)&Ph[(r + 8) * PST + kk + gc + 8];
            }
            #pragma unroll
            for (int nj = 0; nj < 4; nj++) {
                int r = vb + nj * 8 + gr;
                bh[nj][0] = *(const uint32_t*)&Vf[r * PST + kk + gc];
                bh[nj][1] = *(const uint32_t*)&Vf[r * PST + kk + gc + 8];
            }
            #pragma unroll
            for (int mi = 0; mi < 2; mi++)
                #pragma unroll
                for (int nj = 0; nj < 4; nj++) mma16816h(acc[mi][nj], ah[mi], bh[nj]);
        }
    }

    // ---- rowsum combine: 4 threads (t&3) share row prow ----
    rsum += __shfl_xor_sync(0xffffffffu, rsum, 1);
    rsum += __shfl_xor_sync(0xffffffffu, rsum, 2);
    if ((t & 3) == 0) lsum[prow] = rsum;

    // ---- cross-k reduction: wk==1 warps dump acc; wk==0 warps add ----
    float* red = stB;   // reuse stage buffer
    const int w4 = wid & 3;
    __syncthreads();
    if (wk == 1) {
        float* dst = red + (w4 * 32 + lane) * 36;
        #pragma unroll
        for (int mi = 0; mi < 2; mi++)
            #pragma unroll
            for (int nj = 0; nj < 4; nj++)
                *(float4*)&dst[(mi * 4 + nj) * 4] = *(float4*)acc[mi][nj];
    }
    __syncthreads();
    if (wk == 0) {
        const float* src = red + (w4 * 32 + lane) * 36;
        #pragma unroll
        for (int mi = 0; mi < 2; mi++)
            #pragma unroll
            for (int nj = 0; nj < 4; nj++) {
                float4 v = *(const float4*)&src[(mi * 4 + nj) * 4];
                acc[mi][nj][0] += v.x; acc[mi][nj][1] += v.y;
                acc[mi][nj][2] += v.z; acc[mi][nj][3] += v.w;
            }

        const int qb = wm * 32, vb = wn * 32;
        #pragma unroll
        for (int mi = 0; mi < 2; mi++) {
            const int r0 = qb + mi * 16 + gr;
            const float inv0 = 1.f / lsum[r0];
            const float inv1 = 1.f / lsum[r0 + 8];
            #pragma unroll
            for (int nj = 0; nj < 4; nj++) {
                int dk = vb + nj * 8 + gc;
                size_t o0 = ((size_t)(b * SS + q0 + r0)) * DD + h * 64 + dk;
                size_t o1 = ((size_t)(b * SS + q0 + r0 + 8)) * DD + h * 64 + dk;
                bf h0,l0,h1,l1;
                split1(acc[mi][nj][0] * inv0, h0, l0); split1(acc[mi][nj][1] * inv0, h1, l1);
                *(uint32_t*)&g_xh[o0] = pack_bf(h0, h1);
                *(uint32_t*)&g_xl[o0] = pack_bf(l0, l1);
                split1(acc[mi][nj][2] * inv1, h0, l0); split1(acc[mi][nj][3] * inv1, h1, l1);
                *(uint32_t*)&g_xh[o1] = pack_bf(h0, h1);
                *(uint32_t*)&g_xl[o1] = pack_bf(l0, l1);
            }
        }
    }
}

extern "C" void kernel_launch(void* const* d_in, const int* in_sizes, int n_in,
                              void* d_out, int out_size)
{
    // metadata order: query, key, value, bias, mask, W_v, b_v, W_o, b_o
    const float* value = (const float*)d_in[2];
    const float* bias  = (const float*)d_in[3];
    const int*   mask  = (const int*)  d_in[4];
    const float* W_v   = (const float*)d_in[5];
    const float* b_v   = (const float*)d_in[6];
    const float* W_o   = (const float*)d_in[7];
    const float* b_o   = (const float*)d_in[8];

    float* out      = (float*)d_out;                 // [B,S,D]
    float* bias_out = out + (size_t)BB * SS * DD;    // [B,H,S,S]

    cudaFuncSetAttribute(gemm_bf<0>, cudaFuncAttributeMaxDynamicSharedMemorySize, GEMM_SMEM);
    cudaFuncSetAttribute(gemm_bf<1>, cudaFuncAttributeMaxDynamicSharedMemorySize, GEMM_SMEM);
    cudaFuncSetAttribute(attn7, cudaFuncAttributeMaxDynamicSharedMemorySize, ATTN_SMEM);

    bf *p_ah, *p_al, *p_wvh, *p_wvl, *p_woh, *p_wol, *p_xh, *p_xl;
    cudaGetSymbolAddress((void**)&p_ah,  g_ah);
    cudaGetSymbolAddress((void**)&p_al,  g_al);
    cudaGetSymbolAddress((void**)&p_wvh, g_wvh);
    cudaGetSymbolAddress((void**)&p_wvl, g_wvl);
    cudaGetSymbolAddress((void**)&p_woh, g_woh);
    cudaGetSymbolAddress((void**)&p_wol, g_wol);
    cudaGetSymbolAddress((void**)&p_xh,  g_xh);
    cudaGetSymbolAddress((void**)&p_xl,  g_xl);

    // 0) pre-split value, W_v, W_o
    split_prep<<<(N_A4 + 2 * N_W4 + 255) / 256, 256>>>(value, W_v, W_o);

    // 1) V projection -> g_vf fp16 [b][h][dk][s]
    gemm_bf<0><<<dim3(4, 32), 256, GEMM_SMEM>>>(p_ah, p_al, p_wvh, p_wvl, b_v, nullptr);

    // 2) masked softmax(bias) @ v (+ fused bias copy) -> g_xh/g_xl
    attn7<<<dim3(SS / 64, HH, BB), 256, ATTN_SMEM>>>(bias, mask, bias_out);

    // 3) O projection -> out
    gemm_bf<1><<<dim3(4, 32), 256, GEMM_SMEM>>>(p_xh, p_xl, p_woh, p_wol, b_o, out);
}

// round 12
// speedup vs baseline: 1.5141x; 1.1686x over previous
#include <cuda_runtime.h>
#include <cuda_bf16.h>
#include <cuda_fp16.h>
#include <stdint.h>
#include <math.h>

#define BB 4
#define HH 8
#define SS 1024
#define DD 512
#define DKK 64

// Scratch (allocation-free rule: __device__ globals)
__device__ __half g_vf[BB*HH*DKK*SS]; // V projected, fp16, transposed [b][h][dk][s]
__device__ __half g_xf[BB*SS*DD];     // attn out, fp16, [b][s][h*64+dk]
__device__ __half g_af[BB*SS*DD];     // value, fp16
__device__ __half g_wvf[DD*DD];       // W_v, fp16
__device__ __half g_wof[DD*DD];       // W_o, fp16

__device__ __forceinline__ uint32_t pack_h2(float lo, float hi) {
    __half2 h = __floats2half2_rn(lo, hi);
    return *(uint32_t*)&h;
}

// fp16 MMA, fp32 accumulate
__device__ __forceinline__ void mma16816h(float* d, const uint32_t* a, const uint32_t* b) {
    asm volatile(
        "mma.sync.aligned.m16n8k16.row.col.f32.f16.f16.f32 "
        "{%0,%1,%2,%3}, {%4,%5,%6,%7}, {%8,%9}, {%0,%1,%2,%3};"
        : "+f"(d[0]), "+f"(d[1]), "+f"(d[2]), "+f"(d[3])
        : "r"(a[0]), "r"(a[1]), "r"(a[2]), "r"(a[3]), "r"(b[0]), "r"(b[1]));
}

__device__ __forceinline__ uint32_t smem_u32(const void* p) {
    uint32_t a;
    asm("{ .reg .u64 t; cvta.to.shared.u64 t, %1; cvt.u32.u64 %0, t; }" : "=r"(a) : "l"(p));
    return a;
}
__device__ __forceinline__ void cp16(void* s, const void* g) {
    uint32_t sa = smem_u32(s);
    asm volatile("cp.async.cg.shared.global [%0], [%1], 16;" :: "r"(sa), "l"(g));
}
#define CP_COMMIT() asm volatile("cp.async.commit_group;" ::: "memory")

// ======================= prep: fp32 -> fp16 convert =======================
#define N_A4 (BB*SS*DD/4)
#define N_W4 (DD*DD/4)
__global__ void __launch_bounds__(256) half_prep(const float* __restrict__ value,
                                                 const float* __restrict__ Wv,
                                                 const float* __restrict__ Wo)
{
    int i = blockIdx.x * 256 + threadIdx.x;
    const float* src; __half* dst; int base;
    if (i < N_A4)            { src = value; dst = g_af;  base = i; }
    else if (i < N_A4+N_W4)  { src = Wv;    dst = g_wvf; base = i - N_A4; }
    else                     { src = Wo;    dst = g_wof; base = i - N_A4 - N_W4; }
    float4 v = ((const float4*)src)[base];
    *(uint2*)&dst[(size_t)base*4] = make_uint2(pack_h2(v.x, v.y), pack_h2(v.z, v.w));
}

// ============== fp16 tensor-core GEMM, 4-slot cp.async ring, single pass =========
// C = A @ W^T + bv. CTA 128x128, K chunk 32, 8 warps 4m x 2n.
// MODE 0: write V fp16 transposed [b][h][dk][s]. MODE 1: Cout fp32.
#define AST 40
#define GBUF (128 * AST)             // halfs per buffer
#define GSLOT (2 * GBUF)             // Af, Wf
#define GEMM_SMEM (4 * GSLOT * 2)    // 4 slots * 20480B = 81920

template<int MODE>
__global__ void __launch_bounds__(256) gemm_hf(const __half* __restrict__ Af,
                                               const __half* __restrict__ Wf,
                                               const float* __restrict__ bv,
                                               float* __restrict__ Cout)
{
    extern __shared__ __align__(16) char smem[];
    const int t = threadIdx.x, wid = t >> 5, lane = t & 31;
    const int wm = wid & 3, wn = wid >> 2;
    const int n0 = blockIdx.x * 128, m0 = blockIdx.y * 128;
    const int gr = lane >> 2, gc = (lane & 3) * 2;

    float acc[2][8][4];
    #pragma unroll
    for (int i = 0; i < 2; i++)
        #pragma unroll
        for (int j = 0; j < 8; j++)
            #pragma unroll
            for (int q = 0; q < 4; q++) acc[i][j][q] = 0.f;

    // fill: 2 buffers, 512 x 16B segs each, 256 threads -> 2 segs per buffer
    auto fill = [&](int slot, int k0) {
        char* sp = smem + slot * (GSLOT * 2);
        #pragma unroll
        for (int i = 0; i < 4; i++) {
            const int buf = i >> 1;
            const int id  = t + (i & 1) * 256;      // 0..511
            const int row = id >> 2, seg = id & 3;
            const __half* s = buf ? Wf + (size_t)(n0 + row) * 512
                                  : Af + (size_t)(m0 + row) * 512;
            cp16(sp + buf * (GBUF * 2) + row * (AST * 2) + seg * 16, s + k0 + seg * 8);
        }
    };

    fill(0, 0);  CP_COMMIT();
    fill(1, 32); CP_COMMIT();

    for (int c = 0; c < 16; c++) {
        if (c + 2 < 16) { fill((c + 2) & 3, (c + 2) * 32); CP_COMMIT(); }
        if (c < 14)      asm volatile("cp.async.wait_group 2;" ::: "memory");
        else if (c == 14) asm volatile("cp.async.wait_group 1;" ::: "memory");
        else              asm volatile("cp.async.wait_group 0;" ::: "memory");
        __syncthreads();

        char* sp  = smem + (c & 3) * (GSLOT * 2);
        __half* As = (__half*)sp;
        __half* Ws = As + GBUF;

        #pragma unroll
        for (int kk = 0; kk < 32; kk += 16) {
            uint32_t ah[2][4], bh[8][2];
            #pragma unroll
            for (int mi = 0; mi < 2; mi++) {
                int r = wm * 32 + mi * 16 + gr;
                ah[mi][0] = *(const uint32_t*)&As[(r    ) * AST + kk + gc];
                ah[mi][1] = *(const uint32_t*)&As[(r + 8) * AST + kk + gc];
                ah[mi][2] = *(const uint32_t*)&As[(r    ) * AST + kk + gc + 8];
                ah[mi][3] = *(const uint32_t*)&As[(r + 8) * AST + kk + gc + 8];
            }
            #pragma unroll
            for (int nj = 0; nj < 8; nj++) {
                int r = wn * 64 + nj * 8 + gr;
                bh[nj][0] = *(const uint32_t*)&Ws[r * AST + kk + gc];
                bh[nj][1] = *(const uint32_t*)&Ws[r * AST + kk + gc + 8];
            }
            #pragma unroll
            for (int mi = 0; mi < 2; mi++)
                #pragma unroll
                for (int nj = 0; nj < 8; nj++) mma16816h(acc[mi][nj], ah[mi], bh[nj]);
        }
    }

    // ---- epilogue ----
    #pragma unroll
    for (int mi = 0; mi < 2; mi++) {
        int r0 = m0 + wm * 32 + mi * 16 + gr;
        #pragma unroll
        for (int nj = 0; nj < 8; nj++) {
            int n = n0 + wn * 64 + nj * 8 + gc;
            float v00 = acc[mi][nj][0] + bv[n];
            float v01 = acc[mi][nj][1] + bv[n + 1];
            float v10 = acc[mi][nj][2] + bv[n];
            float v11 = acc[mi][nj][3] + bv[n + 1];
            if (MODE == 0) {
                int h_ = n >> 6, d_ = n & 63;
                int b0_ = r0 >> 10, s0_ = r0 & 1023;
                int b1_ = (r0 + 8) >> 10, s1_ = (r0 + 8) & 1023;
                size_t p00 = (((size_t)(b0_ * HH + h_) * DKK) + d_) * SS + s0_;
                size_t p01 = (((size_t)(b0_ * HH + h_) * DKK) + d_ + 1) * SS + s0_;
                size_t p10 = (((size_t)(b1_ * HH + h_) * DKK) + d_) * SS + s1_;
                size_t p11 = (((size_t)(b1_ * HH + h_) * DKK) + d_ + 1) * SS + s1_;
                g_vf[p00] = __float2half(v00);
                g_vf[p01] = __float2half(v01);
                g_vf[p10] = __float2half(v10);
                g_vf[p11] = __float2half(v11);
            } else {
                Cout[(size_t)r0 * 512 + n]           = v00;
                Cout[(size_t)r0 * 512 + n + 1]       = v01;
                Cout[(size_t)(r0 + 8) * 512 + n]     = v10;
                Cout[(size_t)(r0 + 8) * 512 + n + 1] = v11;
            }
        }
    }
}

// ====== attention v7: R8 structure, fp16 single-pass PV (calibrated precision) ======
// 8 warps = 2(m) x 2(n) x 2(k-half). P = fp16(exp(bias) masked), V fp16.
#define PST 72
#define SST 68
#define STAGE_ELEMS (64 * SST)
#define ATTN_SMEM (4 * STAGE_ELEMS * 4 + 2 * 64 * PST * 2 + 256)

__global__ void __launch_bounds__(256, 2) attn7(const float* __restrict__ bias,
                                                const int*   __restrict__ mask,
                                                float*       __restrict__ bias_out)
{
    extern __shared__ __align__(16) char smem[];
    float*  stB  = (float*)smem;
    int*    stM  = (int*)(smem + 2 * STAGE_ELEMS * 4);
    __half* Ph   = (__half*)(smem + 4 * STAGE_ELEMS * 4);
    __half* Vf   = Ph + 64 * PST;
    float*  lsum = (float*)(Vf + 64 * PST);

    const int t = threadIdx.x, wid = t >> 5, lane = t & 31;
    const int gr = lane >> 2, gc = (lane & 3) * 2;
    const int wk = wid >> 2;            // k-half 0/1
    const int wm = (wid >> 1) & 1;      // m-half (32 q rows)
    const int wn = wid & 1;             // n-half (32 dk cols)
    const int q0 = blockIdx.x * 64;
    const int h  = blockIdx.y;
    const int b  = blockIdx.z;

    const float* __restrict__ bias_base = bias     + (((size_t)(b * HH + h)) * SS + q0) * SS;
    float*       __restrict__ bout_base = bias_out + (((size_t)(b * HH + h)) * SS + q0) * SS;
    const int*   __restrict__ mask_base = mask     + ((size_t)(b * SS + q0)) * SS;
    const __half* __restrict__ vf_base  = g_vf + ((size_t)(b * HH + h) * DKK) * SS;

    const int prow = t >> 2;
    const int pc0  = (t & 3) * 16;
    const int vrow = t >> 2;
    const int vc0  = (t & 3) * 16;

    float rsum = 0.f;
    float acc[2][4][4];
    #pragma unroll
    for (int i = 0; i < 2; i++)
        #pragma unroll
        for (int j = 0; j < 4; j++)
            #pragma unroll
            for (int q = 0; q < 4; q++) acc[i][j][q] = 0.f;

    {
        #pragma unroll
        for (int i = 0; i < 4; i++) {
            int o = t + i * 256; int row = o >> 4, seg = o & 15;
            cp16(&stB[row * SST + seg * 4], &bias_base[(size_t)row * SS + seg * 4]);
            cp16(&stM[row * SST + seg * 4], &mask_base[(size_t)row * SS + seg * 4]);
        }
        CP_COMMIT();
    }

    for (int c = 0; c < 16; c++) {
        const int k0 = c * 64;
        if (c < 15) {
            float* dB = stB + ((c + 1) & 1) * STAGE_ELEMS;
            int*   dM = stM + ((c + 1) & 1) * STAGE_ELEMS;
            #pragma unroll
            for (int i = 0; i < 4; i++) {
                int o = t + i * 256; int row = o >> 4, seg = o & 15;
                cp16(&dB[row * SST + seg * 4], &bias_base[(size_t)row * SS + k0 + 64 + seg * 4]);
                cp16(&dM[row * SST + seg * 4], &mask_base[(size_t)row * SS + k0 + 64 + seg * 4]);
            }
            CP_COMMIT();
            asm volatile("cp.async.wait_group 1;" ::: "memory");
        } else {
            asm volatile("cp.async.wait_group 0;" ::: "memory");
        }
        __syncthreads();   // stage ready; prev MMA done (P/V safe to overwrite)

        // ---- issue V LDGs early: latency hidden under P-gen ----
        uint4 vf0, vf1;
        {
            const __half* vf_p = vf_base + (size_t)vrow * SS + k0 + vc0;
            vf0 = *(const uint4*)(vf_p);
            vf1 = *(const uint4*)(vf_p + 8);
        }

        // ---- P gen from staged smem (+ bias copy-out); fp16 ----
        const float* sB = stB + (c & 1) * STAGE_ELEMS + prow * SST + pc0;
        const int*   sM = stM + (c & 1) * STAGE_ELEMS + prow * SST + pc0;
        float*       bo = bout_base + (size_t)prow * SS + k0 + pc0;
        #pragma unroll
        for (int g = 0; g < 4; g++) {
            float4 b4 = *(const float4*)(sB + g * 4);
            int4   m4 = *(const int4*)(sM + g * 4);
            *(float4*)(bo + g * 4) = b4;
            float p0 = m4.x ? __expf(b4.x) : 0.f;
            float p1 = m4.y ? __expf(b4.y) : 0.f;
            float p2 = m4.z ? __expf(b4.z) : 0.f;
            float p3 = m4.w ? __expf(b4.w) : 0.f;
            rsum += (p0 + p1) + (p2 + p3);
            *(uint2*)&Ph[prow * PST + pc0 + g * 4] = make_uint2(pack_h2(p0, p1), pack_h2(p2, p3));
        }

        // ---- store V (arrived by now) ----
        *(uint4*)&Vf[vrow * PST + vc0]     = vf0;
        *(uint4*)&Vf[vrow * PST + vc0 + 8] = vf1;
        __syncthreads();

        // ---- MMA: warp tile m32 x n32 x k32(half), 2 k16 steps, single pass ----
        const int qb = wm * 32, vb = wn * 32, kb = wk * 32;
        #pragma unroll
        for (int kks = 0; kks < 32; kks += 16) {
            const int kk = kb + kks;
            uint32_t ah[2][4], bh[4][2];
            #pragma unroll
            for (int mi = 0; mi < 2; mi++) {
                int r = qb + mi * 16 + gr;
                ah[mi][0] = *(const uint32_t*)&Ph[(r    ) * PST + kk + gc];
                ah[mi][1] = *(const uint32_t*)&Ph[(r + 8) * PST + kk + gc];
                ah[mi][2] = *(const uint32_t*)&Ph[(r    ) * PST + kk + gc + 8];
                ah[mi][3] = *(const uint32_t*)&Ph[(r + 8) * PST + kk + gc + 8];
            }
            #pragma unroll
            for (int nj = 0; nj < 4; nj++) {
                int r = vb + nj * 8 + gr;
                bh[nj][0] = *(const uint32_t*)&Vf[r * PST + kk + gc];
                bh[nj][1] = *(const uint32_t*)&Vf[r * PST + kk + gc + 8];
            }
            #pragma unroll
            for (int mi = 0; mi < 2; mi++)
                #pragma unroll
                for (int nj = 0; nj < 4; nj++) mma16816h(acc[mi][nj], ah[mi], bh[nj]);
        }
    }

    // ---- rowsum combine: 4 threads (t&3) share row prow ----
    rsum += __shfl_xor_sync(0xffffffffu, rsum, 1);
    rsum += __shfl_xor_sync(0xffffffffu, rsum, 2);
    if ((t & 3) == 0) lsum[prow] = rsum;

    // ---- cross-k reduction: wk==1 warps dump acc; wk==0 warps add ----
    float* red = stB;   // reuse stage buffer
    const int w4 = wid & 3;
    __syncthreads();
    if (wk == 1) {
        float* dst = red + (w4 * 32 + lane) * 36;
        #pragma unroll
        for (int mi = 0; mi < 2; mi++)
            #pragma unroll
            for (int nj = 0; nj < 4; nj++)
                *(float4*)&dst[(mi * 4 + nj) * 4] = *(float4*)acc[mi][nj];
    }
    __syncthreads();
    if (wk == 0) {
        const float* src = red + (w4 * 32 + lane) * 36;
        #pragma unroll
        for (int mi = 0; mi < 2; mi++)
            #pragma unroll
            for (int nj = 0; nj < 4; nj++) {
                float4 v = *(const float4*)&src[(mi * 4 + nj) * 4];
                acc[mi][nj][0] += v.x; acc[mi][nj][1] += v.y;
                acc[mi][nj][2] += v.z; acc[mi][nj][3] += v.w;
            }

        const int qb = wm * 32, vb = wn * 32;
        #pragma unroll
        for (int mi = 0; mi < 2; mi++) {
            const int r0 = qb + mi * 16 + gr;
            const float inv0 = 1.f / lsum[r0];
            const float inv1 = 1.f / lsum[r0 + 8];
            #pragma unroll
            for (int nj = 0; nj < 4; nj++) {
                int dk = vb + nj * 8 + gc;
                size_t o0 = ((size_t)(b * SS + q0 + r0)) * DD + h * 64 + dk;
                size_t o1 = ((size_t)(b * SS + q0 + r0 + 8)) * DD + h * 64 + dk;
                *(uint32_t*)&g_xf[o0] = pack_h2(acc[mi][nj][0] * inv0, acc[mi][nj][1] * inv0);
                *(uint32_t*)&g_xf[o1] = pack_h2(acc[mi][nj][2] * inv1, acc[mi][nj][3] * inv1);
            }
        }
    }
}

extern "C" void kernel_launch(void* const* d_in, const int* in_sizes, int n_in,
                              void* d_out, int out_size)
{
    // metadata order: query, key, value, bias, mask, W_v, b_v, W_o, b_o
    const float* value = (const float*)d_in[2];
    const float* bias  = (const float*)d_in[3];
    const int*   mask  = (const int*)  d_in[4];
    const float* W_v   = (const float*)d_in[5];
    const float* b_v   = (const float*)d_in[6];
    const float* W_o   = (const float*)d_in[7];
    const float* b_o   = (const float*)d_in[8];

    float* out      = (float*)d_out;                 // [B,S,D]
    float* bias_out = out + (size_t)BB * SS * DD;    // [B,H,S,S]

    cudaFuncSetAttribute(gemm_hf<0>, cudaFuncAttributeMaxDynamicSharedMemorySize, GEMM_SMEM);
    cudaFuncSetAttribute(gemm_hf<1>, cudaFuncAttributeMaxDynamicSharedMemorySize, GEMM_SMEM);
    cudaFuncSetAttribute(attn7, cudaFuncAttributeMaxDynamicSharedMemorySize, ATTN_SMEM);

    __half *p_af, *p_wvf, *p_wof, *p_xf;
    cudaGetSymbolAddress((void**)&p_af,  g_af);
    cudaGetSymbolAddress((void**)&p_wvf, g_wvf);
    cudaGetSymbolAddress((void**)&p_wof, g_wof);
    cudaGetSymbolAddress((void**)&p_xf,  g_xf);

    // 0) convert value, W_v, W_o to fp16
    half_prep<<<(N_A4 + 2 * N_W4 + 255) / 256, 256>>>(value, W_v, W_o);

    // 1) V projection -> g_vf fp16 [b][h][dk][s]   (fp16 single-pass)
    gemm_hf<0><<<dim3(4, 32), 256, GEMM_SMEM>>>(p_af, p_wvf, b_v, nullptr);

    // 2) masked softmax(bias) @ v (+ fused bias copy) -> g_xf fp16
    attn7<<<dim3(SS / 64, HH, BB), 256, ATTN_SMEM>>>(bias, mask, bias_out);

    // 3) O projection -> out   (fp16 single-pass)
    gemm_hf<1><<<dim3(4, 32), 256, GEMM_SMEM>>>(p_xf, p_wof, b_o, out);
}